// round 1
// baseline (speedup 1.0000x reference)
#include <cuda_runtime.h>
#include <math.h>

#define BB 4
#define NTOK 2048
#define DMODEL 1024
#define NH 16
#define DH 64
#define MROWS (BB * NTOK)            // 8192
#define QKVCOLS (3 * DMODEL)         // 3072

// Scratch (no allocations allowed): fused QKV activations + attention output
__device__ float g_qkv[(size_t)MROWS * QKVCOLS];   // 96 MB
__device__ float g_att[(size_t)MROWS * DMODEL];    // 32 MB

// ---------------------------------------------------------------------------
// Generic tiled SGEMM: C[M,N] = A[M,K] @ B[K,N] + bias[N]
// 64x64 block tile, K-tile 16, 256 threads, 4x4 per thread.
// M, N, K must be multiples of 64/64/16 (true for all our shapes).
// ---------------------------------------------------------------------------
__global__ void sgemm_bias_kernel(const float* __restrict__ A,
                                  const float* __restrict__ Bm,
                                  const float* __restrict__ bias,
                                  float* __restrict__ C,
                                  int M, int N, int K)
{
    __shared__ float As[16][65];   // As[k][m], padded
    __shared__ float Bs[16][65];   // Bs[k][n], padded

    const int tid  = threadIdx.x;
    const int row0 = blockIdx.y * 64;
    const int col0 = blockIdx.x * 64;
    const int tr   = (tid >> 4) * 4;   // thread row base within tile
    const int tc   = (tid & 15) * 4;   // thread col base within tile

    float acc[4][4] = {};

    for (int k0 = 0; k0 < K; k0 += 16) {
        #pragma unroll
        for (int p = 0; p < 4; p++) {
            int idx = tid + p * 256;
            int r = idx >> 4;          // 0..63  (m within tile)
            int c = idx & 15;          // 0..15  (k within tile)
            As[c][r] = A[(size_t)(row0 + r) * K + k0 + c];
        }
        #pragma unroll
        for (int p = 0; p < 4; p++) {
            int idx = tid + p * 256;
            int r = idx >> 6;          // 0..15  (k within tile)
            int c = idx & 63;          // 0..63  (n within tile)
            Bs[r][c] = Bm[(size_t)(k0 + r) * N + col0 + c];
        }
        __syncthreads();

        #pragma unroll
        for (int k = 0; k < 16; k++) {
            float a[4], b[4];
            #pragma unroll
            for (int i = 0; i < 4; i++) a[i] = As[k][tr + i];
            #pragma unroll
            for (int j = 0; j < 4; j++) b[j] = Bs[k][tc + j];
            #pragma unroll
            for (int i = 0; i < 4; i++)
                #pragma unroll
                for (int j = 0; j < 4; j++)
                    acc[i][j] = fmaf(a[i], b[j], acc[i][j]);
        }
        __syncthreads();
    }

    #pragma unroll
    for (int i = 0; i < 4; i++) {
        #pragma unroll
        for (int j = 0; j < 4; j++) {
            C[(size_t)(row0 + tr + i) * N + col0 + tc + j] =
                acc[i][j] + bias[col0 + tc + j];
        }
    }
}

// ---------------------------------------------------------------------------
// Causal flash attention, fp32.
// One block = one (batch, head, 64-query-row tile). 256 threads, 16x16 layout,
// each thread owns a 4x4 patch of the 64x64 score tile and the 64x64 O tile.
// Reads Q/K/V directly (strided) from the fused QKV activation buffer.
// Writes O in [b, n, h*d] layout so the out-proj GEMM is a plain row-major GEMM.
// ---------------------------------------------------------------------------
__global__ void attn_kernel(const float* __restrict__ qkv,
                            float* __restrict__ out)
{
    extern __shared__ float sm[];
    float* Qs = sm;                 // 64 x 65
    float* Ks = Qs + 64 * 65;       // 64 x 65
    float* Vs = Ks + 64 * 65;       // 64 x 65
    float* Ss = Vs + 64 * 65;       // 64 x 65

    const int tid = threadIdx.x;
    const int bh  = blockIdx.y;
    const int b   = bh >> 4;
    const int h   = bh & 15;
    const int qi  = blockIdx.x;      // query tile index (32 tiles)
    const int ty  = tid >> 4;
    const int tx  = tid & 15;
    const int r0  = ty * 4;
    const int c0  = tx * 4;
    const float scale = 0.125f;      // 1/sqrt(64)

    // Load Q tile [64 q-rows x 64 d]
    const size_t qbase = (size_t)(b * NTOK + qi * 64) * QKVCOLS + h * DH;
    #pragma unroll
    for (int p = 0; p < 16; p++) {
        int idx = tid + p * 256;
        int r = idx >> 6, c = idx & 63;
        Qs[r * 65 + c] = qkv[qbase + (size_t)r * QKVCOLS + c];
    }

    float m[4], l[4], acc[4][4] = {};
    #pragma unroll
    for (int i = 0; i < 4; i++) { m[i] = -INFINITY; l[i] = 0.f; }

    const size_t kbase = (size_t)(b * NTOK) * QKVCOLS + DMODEL + h * DH;
    const size_t vbase = kbase + DMODEL;

    for (int j = 0; j <= qi; j++) {
        __syncthreads();   // previous iteration's smem reads complete
        #pragma unroll
        for (int p = 0; p < 16; p++) {
            int idx = tid + p * 256;
            int r = idx >> 6, c = idx & 63;
            size_t rowoff = (size_t)(j * 64 + r) * QKVCOLS + c;
            Ks[r * 65 + c] = qkv[kbase + rowoff];
            Vs[r * 65 + c] = qkv[vbase + rowoff];
        }
        __syncthreads();

        // S = Q @ K^T for this 64x64 tile (4x4 patch per thread)
        float s[4][4] = {};
        #pragma unroll
        for (int d = 0; d < 64; d++) {
            float a[4], kk[4];
            #pragma unroll
            for (int i = 0; i < 4; i++)  a[i]  = Qs[(r0 + i) * 65 + d];
            #pragma unroll
            for (int jj = 0; jj < 4; jj++) kk[jj] = Ks[(c0 + jj) * 65 + d];
            #pragma unroll
            for (int i = 0; i < 4; i++)
                #pragma unroll
                for (int jj = 0; jj < 4; jj++)
                    s[i][jj] = fmaf(a[i], kk[jj], s[i][jj]);
        }

        // scale + causal mask (mask only relevant on the diagonal tile)
        if (j == qi) {
            #pragma unroll
            for (int i = 0; i < 4; i++)
                #pragma unroll
                for (int jj = 0; jj < 4; jj++)
                    s[i][jj] = (c0 + jj <= r0 + i) ? s[i][jj] * scale : -INFINITY;
        } else {
            #pragma unroll
            for (int i = 0; i < 4; i++)
                #pragma unroll
                for (int jj = 0; jj < 4; jj++)
                    s[i][jj] *= scale;
        }

        // online softmax update per row (rows shared across the 16 tx threads)
        #pragma unroll
        for (int i = 0; i < 4; i++) {
            float mx = fmaxf(fmaxf(s[i][0], s[i][1]), fmaxf(s[i][2], s[i][3]));
            #pragma unroll
            for (int o = 8; o >= 1; o >>= 1)
                mx = fmaxf(mx, __shfl_xor_sync(0xffffffffu, mx, o));
            float mnew  = fmaxf(m[i], mx);
            float alpha = expf(m[i] - mnew);   // exp(-inf)=0 on first tile
            float sum = 0.f;
            #pragma unroll
            for (int jj = 0; jj < 4; jj++) {
                float p = expf(s[i][jj] - mnew);
                Ss[(r0 + i) * 65 + c0 + jj] = p;
                sum += p;
            }
            #pragma unroll
            for (int o = 8; o >= 1; o >>= 1)
                sum += __shfl_xor_sync(0xffffffffu, sum, o);
            l[i] = l[i] * alpha + sum;
            m[i] = mnew;
            #pragma unroll
            for (int jj = 0; jj < 4; jj++) acc[i][jj] *= alpha;
        }
        __syncthreads();

        // O += P @ V  (thread's O patch: rows r0.., d-cols c0..)
        #pragma unroll
        for (int kv = 0; kv < 64; kv++) {
            float pv[4], vv[4];
            #pragma unroll
            for (int i = 0; i < 4; i++)  pv[i] = Ss[(r0 + i) * 65 + kv];
            #pragma unroll
            for (int jj = 0; jj < 4; jj++) vv[jj] = Vs[kv * 65 + c0 + jj];
            #pragma unroll
            for (int i = 0; i < 4; i++)
                #pragma unroll
                for (int jj = 0; jj < 4; jj++)
                    acc[i][jj] = fmaf(pv[i], vv[jj], acc[i][jj]);
        }
    }

    // normalize and store in [b, n, h*d] layout
    #pragma unroll
    for (int i = 0; i < 4; i++) {
        float inv = 1.f / l[i];
        size_t obase = (size_t)(b * NTOK + qi * 64 + r0 + i) * DMODEL + h * DH + c0;
        #pragma unroll
        for (int jj = 0; jj < 4; jj++)
            out[obase + jj] = acc[i][jj] * inv;
    }
}

// ---------------------------------------------------------------------------
extern "C" void kernel_launch(void* const* d_in, const int* in_sizes, int n_in,
                              void* d_out, int out_size)
{
    const float* x     = (const float*)d_in[0];
    const float* w_qkv = (const float*)d_in[1];
    const float* b_qkv = (const float*)d_in[2];
    const float* w_out = (const float*)d_in[3];
    const float* b_out = (const float*)d_in[4];
    float* out = (float*)d_out;

    float* qkv;  cudaGetSymbolAddress((void**)&qkv, g_qkv);
    float* att;  cudaGetSymbolAddress((void**)&att, g_att);

    // 1) QKV projection: [8192,1024] @ [1024,3072] + bias
    {
        dim3 grid(QKVCOLS / 64, MROWS / 64);
        sgemm_bias_kernel<<<grid, 256>>>(x, w_qkv, b_qkv, qkv,
                                         MROWS, QKVCOLS, DMODEL);
    }

    // 2) causal flash attention
    {
        const int smem = 4 * 64 * 65 * sizeof(float);  // 66560 B
        cudaFuncSetAttribute(attn_kernel,
                             cudaFuncAttributeMaxDynamicSharedMemorySize, smem);
        dim3 grid(NTOK / 64, BB * NH);
        attn_kernel<<<grid, 256, smem>>>(qkv, att);
    }

    // 3) output projection: [8192,1024] @ [1024,1024] + bias
    {
        dim3 grid(DMODEL / 64, MROWS / 64);
        sgemm_bias_kernel<<<grid, 256>>>(att, w_out, b_out, out,
                                         MROWS, DMODEL, DMODEL);
    }
}

// round 2
// speedup vs baseline: 1.9234x; 1.9234x over previous
#include <cuda_runtime.h>
#include <math.h>
#include <stdint.h>

#define BB 4
#define NTOK 2048
#define DMODEL 1024
#define NH 16
#define DH 64
#define MROWS (BB * NTOK)            // 8192
#define QKVCOLS (3 * DMODEL)         // 3072

// Scratch (no allocations allowed): fused QKV activations + attention output
__device__ float g_qkv[(size_t)MROWS * QKVCOLS];   // 96 MB
__device__ float g_att[(size_t)MROWS * DMODEL];    // 32 MB

// ---------------------------------------------------------------------------
// TF32 tensor-core GEMM: C[M,N] = A[M,K] @ B[K,N] + bias[N]
// CTA tile 128x128, K-tile 32. 256 threads = 8 warps (2x4), warp tile 64x32.
// mma.sync.aligned.m16n8k8.row.col.f32.tf32.tf32.f32
// As[m][k] pad->36 (A-frag LDS conflict-free: bank=(4m+k)%32).
// Bs[k][n] pad->132, stored untransposed (float4 STS), B-frag gather <=2-way.
// ---------------------------------------------------------------------------
#define BK 32
#define APAD 36
#define BPAD 132

__device__ __forceinline__ uint32_t f2tf32(float x) {
    uint32_t u;
    asm volatile("cvt.rna.tf32.f32 %0, %1;" : "=r"(u) : "f"(x));
    return u;
}

__global__ __launch_bounds__(256) void gemm_tf32_bias(
    const float* __restrict__ A,
    const float* __restrict__ B,
    const float* __restrict__ bias,
    float* __restrict__ C,
    int M, int N, int K)
{
    __shared__ uint32_t As[128 * APAD];   // [m][k]
    __shared__ uint32_t Bs[BK * BPAD];    // [k][n]

    const int tid  = threadIdx.x;
    const int lane = tid & 31;
    const int wid  = tid >> 5;
    const int row0 = blockIdx.y * 128;
    const int col0 = blockIdx.x * 128;

    // warp layout: 2 (m) x 4 (n); warp tile 64x32
    const int wm0 = (wid >> 2) * 64;
    const int wn0 = (wid & 3) * 32;
    const int gr  = lane >> 2;   // groupID 0..7
    const int gc  = lane & 3;    // threadID in group 0..3

    // global load mapping
    const int arow = tid >> 3;          // 0..31 (+p*32)
    const int acol = (tid & 7) * 4;     // float4 col
    const int brow = tid >> 5;          // 0..7  (+p*8)
    const int bcol = (tid & 31) * 4;

    float4 aReg[4], bReg[4];
    const int niter = K / BK;

    // prefetch tile 0
    #pragma unroll
    for (int p = 0; p < 4; p++) {
        aReg[p] = *(const float4*)&A[(size_t)(row0 + arow + p * 32) * K + acol];
        bReg[p] = *(const float4*)&B[(size_t)(brow + p * 8) * N + col0 + bcol];
    }

    float acc[4][4][4];
    #pragma unroll
    for (int i = 0; i < 4; i++)
        #pragma unroll
        for (int j = 0; j < 4; j++)
            #pragma unroll
            for (int q = 0; q < 4; q++) acc[i][j][q] = 0.f;

    for (int it = 0; it < niter; it++) {
        // store prefetched tile to smem (convert to tf32)
        #pragma unroll
        for (int p = 0; p < 4; p++) {
            uint32_t* as = &As[(arow + p * 32) * APAD + acol];
            as[0] = f2tf32(aReg[p].x); as[1] = f2tf32(aReg[p].y);
            as[2] = f2tf32(aReg[p].z); as[3] = f2tf32(aReg[p].w);
            uint32_t* bs = &Bs[(brow + p * 8) * BPAD + bcol];
            bs[0] = f2tf32(bReg[p].x); bs[1] = f2tf32(bReg[p].y);
            bs[2] = f2tf32(bReg[p].z); bs[3] = f2tf32(bReg[p].w);
        }
        __syncthreads();

        // prefetch next tile
        if (it + 1 < niter) {
            int k0 = (it + 1) * BK;
            #pragma unroll
            for (int p = 0; p < 4; p++) {
                aReg[p] = *(const float4*)&A[(size_t)(row0 + arow + p * 32) * K + k0 + acol];
                bReg[p] = *(const float4*)&B[(size_t)(k0 + brow + p * 8) * N + col0 + bcol];
            }
        }

        // compute: 4 ksteps of 8
        #pragma unroll
        for (int kk = 0; kk < 4; kk++) {
            const int kb = kk * 8;
            uint32_t af[4][4], bf[4][2];
            #pragma unroll
            for (int mt = 0; mt < 4; mt++) {
                const uint32_t* base = &As[(wm0 + mt * 16 + gr) * APAD + kb + gc];
                af[mt][0] = base[0];
                af[mt][1] = base[8 * APAD];
                af[mt][2] = base[4];
                af[mt][3] = base[8 * APAD + 4];
            }
            #pragma unroll
            for (int nt = 0; nt < 4; nt++) {
                const uint32_t* base = &Bs[(kb + gc) * BPAD + wn0 + nt * 8 + gr];
                bf[nt][0] = base[0];
                bf[nt][1] = base[4 * BPAD];
            }
            #pragma unroll
            for (int mt = 0; mt < 4; mt++)
                #pragma unroll
                for (int nt = 0; nt < 4; nt++) {
                    asm volatile(
                        "mma.sync.aligned.m16n8k8.row.col.f32.tf32.tf32.f32 "
                        "{%0,%1,%2,%3}, {%4,%5,%6,%7}, {%8,%9}, {%0,%1,%2,%3};"
                        : "+f"(acc[mt][nt][0]), "+f"(acc[mt][nt][1]),
                          "+f"(acc[mt][nt][2]), "+f"(acc[mt][nt][3])
                        : "r"(af[mt][0]), "r"(af[mt][1]), "r"(af[mt][2]), "r"(af[mt][3]),
                          "r"(bf[nt][0]), "r"(bf[nt][1]));
                }
        }
        __syncthreads();
    }

    // epilogue: add bias, store
    #pragma unroll
    for (int mt = 0; mt < 4; mt++) {
        int r = row0 + wm0 + mt * 16 + gr;
        #pragma unroll
        for (int nt = 0; nt < 4; nt++) {
            int c = col0 + wn0 + nt * 8 + 2 * gc;
            float bv0 = bias[c], bv1 = bias[c + 1];
            C[(size_t)r * N + c]           = acc[mt][nt][0] + bv0;
            C[(size_t)r * N + c + 1]       = acc[mt][nt][1] + bv1;
            C[(size_t)(r + 8) * N + c]     = acc[mt][nt][2] + bv0;
            C[(size_t)(r + 8) * N + c + 1] = acc[mt][nt][3] + bv1;
        }
    }
}

// ---------------------------------------------------------------------------
// Causal flash attention, fp32 (unchanged from R1 — known good).
// ---------------------------------------------------------------------------
__global__ void attn_kernel(const float* __restrict__ qkv,
                            float* __restrict__ out)
{
    extern __shared__ float sm[];
    float* Qs = sm;                 // 64 x 65
    float* Ks = Qs + 64 * 65;       // 64 x 65
    float* Vs = Ks + 64 * 65;       // 64 x 65
    float* Ss = Vs + 64 * 65;       // 64 x 65

    const int tid = threadIdx.x;
    const int bh  = blockIdx.y;
    const int b   = bh >> 4;
    const int h   = bh & 15;
    const int qi  = blockIdx.x;
    const int ty  = tid >> 4;
    const int tx  = tid & 15;
    const int r0  = ty * 4;
    const int c0  = tx * 4;
    const float scale = 0.125f;

    const size_t qbase = (size_t)(b * NTOK + qi * 64) * QKVCOLS + h * DH;
    #pragma unroll
    for (int p = 0; p < 16; p++) {
        int idx = tid + p * 256;
        int r = idx >> 6, c = idx & 63;
        Qs[r * 65 + c] = qkv[qbase + (size_t)r * QKVCOLS + c];
    }

    float m[4], l[4], acc[4][4] = {};
    #pragma unroll
    for (int i = 0; i < 4; i++) { m[i] = -INFINITY; l[i] = 0.f; }

    const size_t kbase = (size_t)(b * NTOK) * QKVCOLS + DMODEL + h * DH;
    const size_t vbase = kbase + DMODEL;

    for (int j = 0; j <= qi; j++) {
        __syncthreads();
        #pragma unroll
        for (int p = 0; p < 16; p++) {
            int idx = tid + p * 256;
            int r = idx >> 6, c = idx & 63;
            size_t rowoff = (size_t)(j * 64 + r) * QKVCOLS + c;
            Ks[r * 65 + c] = qkv[kbase + rowoff];
            Vs[r * 65 + c] = qkv[vbase + rowoff];
        }
        __syncthreads();

        float s[4][4] = {};
        #pragma unroll
        for (int d = 0; d < 64; d++) {
            float a[4], kk[4];
            #pragma unroll
            for (int i = 0; i < 4; i++)  a[i]  = Qs[(r0 + i) * 65 + d];
            #pragma unroll
            for (int jj = 0; jj < 4; jj++) kk[jj] = Ks[(c0 + jj) * 65 + d];
            #pragma unroll
            for (int i = 0; i < 4; i++)
                #pragma unroll
                for (int jj = 0; jj < 4; jj++)
                    s[i][jj] = fmaf(a[i], kk[jj], s[i][jj]);
        }

        if (j == qi) {
            #pragma unroll
            for (int i = 0; i < 4; i++)
                #pragma unroll
                for (int jj = 0; jj < 4; jj++)
                    s[i][jj] = (c0 + jj <= r0 + i) ? s[i][jj] * scale : -INFINITY;
        } else {
            #pragma unroll
            for (int i = 0; i < 4; i++)
                #pragma unroll
                for (int jj = 0; jj < 4; jj++)
                    s[i][jj] *= scale;
        }

        #pragma unroll
        for (int i = 0; i < 4; i++) {
            float mx = fmaxf(fmaxf(s[i][0], s[i][1]), fmaxf(s[i][2], s[i][3]));
            #pragma unroll
            for (int o = 8; o >= 1; o >>= 1)
                mx = fmaxf(mx, __shfl_xor_sync(0xffffffffu, mx, o));
            float mnew  = fmaxf(m[i], mx);
            float alpha = expf(m[i] - mnew);
            float sum = 0.f;
            #pragma unroll
            for (int jj = 0; jj < 4; jj++) {
                float p = expf(s[i][jj] - mnew);
                Ss[(r0 + i) * 65 + c0 + jj] = p;
                sum += p;
            }
            #pragma unroll
            for (int o = 8; o >= 1; o >>= 1)
                sum += __shfl_xor_sync(0xffffffffu, sum, o);
            l[i] = l[i] * alpha + sum;
            m[i] = mnew;
            #pragma unroll
            for (int jj = 0; jj < 4; jj++) acc[i][jj] *= alpha;
        }
        __syncthreads();

        #pragma unroll
        for (int kv = 0; kv < 64; kv++) {
            float pv[4], vv[4];
            #pragma unroll
            for (int i = 0; i < 4; i++)  pv[i] = Ss[(r0 + i) * 65 + kv];
            #pragma unroll
            for (int jj = 0; jj < 4; jj++) vv[jj] = Vs[kv * 65 + c0 + jj];
            #pragma unroll
            for (int i = 0; i < 4; i++)
                #pragma unroll
                for (int jj = 0; jj < 4; jj++)
                    acc[i][jj] = fmaf(pv[i], vv[jj], acc[i][jj]);
        }
    }

    #pragma unroll
    for (int i = 0; i < 4; i++) {
        float inv = 1.f / l[i];
        size_t obase = (size_t)(b * NTOK + qi * 64 + r0 + i) * DMODEL + h * DH + c0;
        #pragma unroll
        for (int jj = 0; jj < 4; jj++)
            out[obase + jj] = acc[i][jj] * inv;
    }
}

// ---------------------------------------------------------------------------
extern "C" void kernel_launch(void* const* d_in, const int* in_sizes, int n_in,
                              void* d_out, int out_size)
{
    const float* x     = (const float*)d_in[0];
    const float* w_qkv = (const float*)d_in[1];
    const float* b_qkv = (const float*)d_in[2];
    const float* w_out = (const float*)d_in[3];
    const float* b_out = (const float*)d_in[4];
    float* out = (float*)d_out;

    float* qkv;  cudaGetSymbolAddress((void**)&qkv, g_qkv);
    float* att;  cudaGetSymbolAddress((void**)&att, g_att);

    // 1) QKV projection: [8192,1024] @ [1024,3072] + bias  (tf32 tensor cores)
    {
        dim3 grid(QKVCOLS / 128, MROWS / 128);   // 24 x 64
        gemm_tf32_bias<<<grid, 256>>>(x, w_qkv, b_qkv, qkv,
                                      MROWS, QKVCOLS, DMODEL);
    }

    // 2) causal flash attention (fp32)
    {
        const int smem = 4 * 64 * 65 * sizeof(float);  // 66560 B
        cudaFuncSetAttribute(attn_kernel,
                             cudaFuncAttributeMaxDynamicSharedMemorySize, smem);
        dim3 grid(NTOK / 64, BB * NH);
        attn_kernel<<<grid, 256, smem>>>(qkv, att);
    }

    // 3) output projection: [8192,1024] @ [1024,1024] + bias  (tf32 tensor cores)
    {
        dim3 grid(DMODEL / 128, MROWS / 128);    // 8 x 64
        gemm_tf32_bias<<<grid, 256>>>(att, w_out, b_out, out,
                                      MROWS, DMODEL, DMODEL);
    }
}

// round 3
// speedup vs baseline: 3.9286x; 2.0426x over previous
#include <cuda_runtime.h>
#include <math.h>
#include <stdint.h>

#define BB 4
#define NTOK 2048
#define DMODEL 1024
#define NH 16
#define DH 64
#define MROWS (BB * NTOK)            // 8192
#define QKVCOLS (3 * DMODEL)         // 3072

// Scratch (no allocations allowed)
__device__ float g_qkv[(size_t)MROWS * QKVCOLS];   // 96 MB
__device__ float g_att[(size_t)MROWS * DMODEL];    // 32 MB

__device__ __forceinline__ uint32_t f2tf32(float x) {
    uint32_t u;
    asm volatile("cvt.rna.tf32.f32 %0, %1;" : "=r"(u) : "f"(x));
    return u;
}

// ---------------------------------------------------------------------------
// TF32 tensor-core GEMM: C[M,N] = A[M,K] @ B[K,N] + bias[N]
// 128x128 CTA tile, BK=32, 256 threads (8 warps, 64x32 warp tile).
// ---------------------------------------------------------------------------
#define BK 32
#define APAD 36
#define BPAD 132

__global__ __launch_bounds__(256, 2) void gemm_tf32_bias(
    const float* __restrict__ A,
    const float* __restrict__ B,
    const float* __restrict__ bias,
    float* __restrict__ C,
    int M, int N, int K)
{
    __shared__ uint32_t As[128 * APAD];
    __shared__ uint32_t Bs[BK * BPAD];

    const int tid  = threadIdx.x;
    const int lane = tid & 31;
    const int wid  = tid >> 5;
    const int row0 = blockIdx.y * 128;
    const int col0 = blockIdx.x * 128;

    const int wm0 = (wid >> 2) * 64;
    const int wn0 = (wid & 3) * 32;
    const int gr  = lane >> 2;
    const int gc  = lane & 3;

    const int arow = tid >> 3;
    const int acol = (tid & 7) * 4;
    const int brow = tid >> 5;
    const int bcol = (tid & 31) * 4;

    float4 aReg[4], bReg[4];
    const int niter = K / BK;

    #pragma unroll
    for (int p = 0; p < 4; p++) {
        aReg[p] = *(const float4*)&A[(size_t)(row0 + arow + p * 32) * K + acol];
        bReg[p] = *(const float4*)&B[(size_t)(brow + p * 8) * N + col0 + bcol];
    }

    float acc[4][4][4];
    #pragma unroll
    for (int i = 0; i < 4; i++)
        #pragma unroll
        for (int j = 0; j < 4; j++)
            #pragma unroll
            for (int q = 0; q < 4; q++) acc[i][j][q] = 0.f;

    for (int it = 0; it < niter; it++) {
        #pragma unroll
        for (int p = 0; p < 4; p++) {
            uint32_t* as = &As[(arow + p * 32) * APAD + acol];
            as[0] = f2tf32(aReg[p].x); as[1] = f2tf32(aReg[p].y);
            as[2] = f2tf32(aReg[p].z); as[3] = f2tf32(aReg[p].w);
            uint32_t* bs = &Bs[(brow + p * 8) * BPAD + bcol];
            bs[0] = f2tf32(bReg[p].x); bs[1] = f2tf32(bReg[p].y);
            bs[2] = f2tf32(bReg[p].z); bs[3] = f2tf32(bReg[p].w);
        }
        __syncthreads();

        if (it + 1 < niter) {
            int k0 = (it + 1) * BK;
            #pragma unroll
            for (int p = 0; p < 4; p++) {
                aReg[p] = *(const float4*)&A[(size_t)(row0 + arow + p * 32) * K + k0 + acol];
                bReg[p] = *(const float4*)&B[(size_t)(k0 + brow + p * 8) * N + col0 + bcol];
            }
        }

        #pragma unroll
        for (int kk = 0; kk < 4; kk++) {
            const int kb = kk * 8;
            uint32_t af[4][4], bf[4][2];
            #pragma unroll
            for (int mt = 0; mt < 4; mt++) {
                const uint32_t* base = &As[(wm0 + mt * 16 + gr) * APAD + kb + gc];
                af[mt][0] = base[0];
                af[mt][1] = base[8 * APAD];
                af[mt][2] = base[4];
                af[mt][3] = base[8 * APAD + 4];
            }
            #pragma unroll
            for (int nt = 0; nt < 4; nt++) {
                const uint32_t* base = &Bs[(kb + gc) * BPAD + wn0 + nt * 8 + gr];
                bf[nt][0] = base[0];
                bf[nt][1] = base[4 * BPAD];
            }
            #pragma unroll
            for (int mt = 0; mt < 4; mt++)
                #pragma unroll
                for (int nt = 0; nt < 4; nt++) {
                    asm volatile(
                        "mma.sync.aligned.m16n8k8.row.col.f32.tf32.tf32.f32 "
                        "{%0,%1,%2,%3}, {%4,%5,%6,%7}, {%8,%9}, {%0,%1,%2,%3};"
                        : "+f"(acc[mt][nt][0]), "+f"(acc[mt][nt][1]),
                          "+f"(acc[mt][nt][2]), "+f"(acc[mt][nt][3])
                        : "r"(af[mt][0]), "r"(af[mt][1]), "r"(af[mt][2]), "r"(af[mt][3]),
                          "r"(bf[nt][0]), "r"(bf[nt][1]));
                }
        }
        __syncthreads();
    }

    #pragma unroll
    for (int mt = 0; mt < 4; mt++) {
        int r = row0 + wm0 + mt * 16 + gr;
        #pragma unroll
        for (int nt = 0; nt < 4; nt++) {
            int c = col0 + wn0 + nt * 8 + 2 * gc;
            float bv0 = bias[c], bv1 = bias[c + 1];
            C[(size_t)r * N + c]           = acc[mt][nt][0] + bv0;
            C[(size_t)r * N + c + 1]       = acc[mt][nt][1] + bv1;
            C[(size_t)(r + 8) * N + c]     = acc[mt][nt][2] + bv0;
            C[(size_t)(r + 8) * N + c + 1] = acc[mt][nt][3] + bv1;
        }
    }
}

// ---------------------------------------------------------------------------
// TF32 tensor-core causal flash attention.
// CTA = (b, h, 128-query-row tile). 256 threads = 8 warps; warp owns 16 q-rows.
// KV tiles of 64. S and PV via mma.m16n8k8.tf32; softmax fp32 in registers.
// Smem (dynamic): Qs[128][68] Ks[64][68] Vs[64][68] Ps[128][68]  (tf32 u32)
// Pad 68 (68%32==4): A-type frag loads conflict-free; B-type <=2-way.
// ---------------------------------------------------------------------------
#define QT 128
#define KT 64
#define QPAD 68

__global__ __launch_bounds__(256, 2) void attn_tf32(
    const float* __restrict__ qkv, float* __restrict__ out)
{
    extern __shared__ uint32_t sm_u[];
    uint32_t* Qs = sm_u;                       // 128*68
    uint32_t* Ks = Qs + QT * QPAD;             // 64*68
    uint32_t* Vs = Ks + KT * QPAD;             // 64*68
    uint32_t* Ps = Vs + KT * QPAD;             // 128*68

    const int tid  = threadIdx.x;
    const int lane = tid & 31;
    const int wid  = tid >> 5;
    const int gr   = lane >> 2;
    const int gc   = lane & 3;

    const int bh = blockIdx.x;
    const int b  = bh >> 4;
    const int h  = bh & 15;
    const int qi = (gridDim.y - 1) - blockIdx.y;   // heavy tiles first
    const int q0 = qi * QT;
    const float scale = 0.125f;

    // ---- load Q tile [128 x 64] -> tf32 smem ----
    {
        const size_t qbase = (size_t)(b * NTOK + q0) * QKVCOLS + h * DH;
        #pragma unroll
        for (int p = 0; p < 8; p++) {
            int idx = tid + p * 256;          // float4 index over 128*16
            int r = idx >> 4, c = (idx & 15) * 4;
            float4 v = *(const float4*)&qkv[qbase + (size_t)r * QKVCOLS + c];
            uint32_t* d = &Qs[r * QPAD + c];
            d[0] = f2tf32(v.x); d[1] = f2tf32(v.y);
            d[2] = f2tf32(v.z); d[3] = f2tf32(v.w);
        }
    }

    float accO[8][4];
    #pragma unroll
    for (int nt = 0; nt < 8; nt++)
        #pragma unroll
        for (int q = 0; q < 4; q++) accO[nt][q] = 0.f;
    float mrow[2] = { -INFINITY, -INFINITY };
    float lrow[2] = { 0.f, 0.f };

    const size_t kvbase = (size_t)(b * NTOK) * QKVCOLS + DMODEL + h * DH;
    const int nkv = 2 * qi + 2;
    const int wrow0 = q0 + wid * 16;          // warp's first q row (global)

    for (int j = 0; j < nkv; j++) {
        __syncthreads();                       // smem reuse guard
        // ---- load K,V tile [64 x 64] each ----
        {
            #pragma unroll
            for (int p = 0; p < 4; p++) {
                int idx = tid + p * 256;       // float4 index over 64*16
                int r = idx >> 4, c = (idx & 15) * 4;
                size_t off = kvbase + (size_t)(j * KT + r) * QKVCOLS + c;
                float4 kv4 = *(const float4*)&qkv[off];
                float4 vv4 = *(const float4*)&qkv[off + DMODEL];
                uint32_t* dk = &Ks[r * QPAD + c];
                dk[0] = f2tf32(kv4.x); dk[1] = f2tf32(kv4.y);
                dk[2] = f2tf32(kv4.z); dk[3] = f2tf32(kv4.w);
                uint32_t* dv = &Vs[r * QPAD + c];
                dv[0] = f2tf32(vv4.x); dv[1] = f2tf32(vv4.y);
                dv[2] = f2tf32(vv4.z); dv[3] = f2tf32(vv4.w);
            }
        }
        __syncthreads();

        // warp entirely masked? (all its rows < first kv col of tile)
        if (j * KT > wrow0 + 15) continue;

        // ---- S = Q @ K^T (16 x 64 per warp) ----
        float s[8][4];
        #pragma unroll
        for (int nt = 0; nt < 8; nt++)
            #pragma unroll
            for (int q = 0; q < 4; q++) s[nt][q] = 0.f;

        #pragma unroll
        for (int kb = 0; kb < 8; kb++) {
            const uint32_t* abase = &Qs[(wid * 16 + gr) * QPAD + kb * 8 + gc];
            uint32_t a0 = abase[0], a1 = abase[8 * QPAD];
            uint32_t a2 = abase[4], a3 = abase[8 * QPAD + 4];
            #pragma unroll
            for (int nt = 0; nt < 8; nt++) {
                const uint32_t* bbase = &Ks[(nt * 8 + gr) * QPAD + kb * 8 + gc];
                uint32_t b0 = bbase[0], b1 = bbase[4];
                asm volatile(
                    "mma.sync.aligned.m16n8k8.row.col.f32.tf32.tf32.f32 "
                    "{%0,%1,%2,%3}, {%4,%5,%6,%7}, {%8,%9}, {%0,%1,%2,%3};"
                    : "+f"(s[nt][0]), "+f"(s[nt][1]), "+f"(s[nt][2]), "+f"(s[nt][3])
                    : "r"(a0), "r"(a1), "r"(a2), "r"(a3), "r"(b0), "r"(b1));
            }
        }

        // ---- scale + causal mask ----
        if (j * KT + KT - 1 <= wrow0) {
            #pragma unroll
            for (int nt = 0; nt < 8; nt++)
                #pragma unroll
                for (int q = 0; q < 4; q++) s[nt][q] *= scale;
        } else {
            const int r0g = wrow0 + gr, r1g = wrow0 + gr + 8;
            #pragma unroll
            for (int nt = 0; nt < 8; nt++) {
                int c0g = j * KT + nt * 8 + 2 * gc;
                s[nt][0] = (c0g     <= r0g) ? s[nt][0] * scale : -INFINITY;
                s[nt][1] = (c0g + 1 <= r0g) ? s[nt][1] * scale : -INFINITY;
                s[nt][2] = (c0g     <= r1g) ? s[nt][2] * scale : -INFINITY;
                s[nt][3] = (c0g + 1 <= r1g) ? s[nt][3] * scale : -INFINITY;
            }
        }

        // ---- online softmax (per half: rows gr / gr+8) ----
        #pragma unroll
        for (int half = 0; half < 2; half++) {
            float tmax = -INFINITY;
            #pragma unroll
            for (int nt = 0; nt < 8; nt++)
                tmax = fmaxf(tmax, fmaxf(s[nt][2 * half], s[nt][2 * half + 1]));
            tmax = fmaxf(tmax, __shfl_xor_sync(0xffffffffu, tmax, 1));
            tmax = fmaxf(tmax, __shfl_xor_sync(0xffffffffu, tmax, 2));
            float mnew  = fmaxf(mrow[half], tmax);
            float alpha = __expf(mrow[half] - mnew);
            float sum = 0.f;
            const int prow = (wid * 16 + gr + 8 * half) * QPAD;
            #pragma unroll
            for (int nt = 0; nt < 8; nt++) {
                float p0 = __expf(s[nt][2 * half]     - mnew);
                float p1 = __expf(s[nt][2 * half + 1] - mnew);
                sum += p0 + p1;
                Ps[prow + nt * 8 + 2 * gc]     = f2tf32(p0);
                Ps[prow + nt * 8 + 2 * gc + 1] = f2tf32(p1);
            }
            sum += __shfl_xor_sync(0xffffffffu, sum, 1);
            sum += __shfl_xor_sync(0xffffffffu, sum, 2);
            lrow[half] = lrow[half] * alpha + sum;
            mrow[half] = mnew;
            #pragma unroll
            for (int nt = 0; nt < 8; nt++) {
                accO[nt][2 * half]     *= alpha;
                accO[nt][2 * half + 1] *= alpha;
            }
        }
        __syncwarp();

        // ---- O += P @ V ----
        #pragma unroll
        for (int kb = 0; kb < 8; kb++) {
            const uint32_t* abase = &Ps[(wid * 16 + gr) * QPAD + kb * 8 + gc];
            uint32_t a0 = abase[0], a1 = abase[8 * QPAD];
            uint32_t a2 = abase[4], a3 = abase[8 * QPAD + 4];
            #pragma unroll
            for (int nt = 0; nt < 8; nt++) {
                uint32_t b0 = Vs[(kb * 8 + gc) * QPAD + nt * 8 + gr];
                uint32_t b1 = Vs[(kb * 8 + gc + 4) * QPAD + nt * 8 + gr];
                asm volatile(
                    "mma.sync.aligned.m16n8k8.row.col.f32.tf32.tf32.f32 "
                    "{%0,%1,%2,%3}, {%4,%5,%6,%7}, {%8,%9}, {%0,%1,%2,%3};"
                    : "+f"(accO[nt][0]), "+f"(accO[nt][1]),
                      "+f"(accO[nt][2]), "+f"(accO[nt][3])
                    : "r"(a0), "r"(a1), "r"(a2), "r"(a3), "r"(b0), "r"(b1));
            }
        }
    }

    // ---- epilogue: normalize, write [b, n, h*d] ----
    float inv0 = 1.f / lrow[0];
    float inv1 = 1.f / lrow[1];
    size_t r0 = (size_t)(b * NTOK + wrow0 + gr) * DMODEL + h * DH;
    size_t r1 = r0 + 8 * DMODEL;
    #pragma unroll
    for (int nt = 0; nt < 8; nt++) {
        int c = nt * 8 + 2 * gc;
        *(float2*)&out[r0 + c] = make_float2(accO[nt][0] * inv0, accO[nt][1] * inv0);
        *(float2*)&out[r1 + c] = make_float2(accO[nt][2] * inv1, accO[nt][3] * inv1);
    }
}

// ---------------------------------------------------------------------------
extern "C" void kernel_launch(void* const* d_in, const int* in_sizes, int n_in,
                              void* d_out, int out_size)
{
    const float* x     = (const float*)d_in[0];
    const float* w_qkv = (const float*)d_in[1];
    const float* b_qkv = (const float*)d_in[2];
    const float* w_out = (const float*)d_in[3];
    const float* b_out = (const float*)d_in[4];
    float* out = (float*)d_out;

    float* qkv;  cudaGetSymbolAddress((void**)&qkv, g_qkv);
    float* att;  cudaGetSymbolAddress((void**)&att, g_att);

    // 1) QKV projection (tf32 tensor cores)
    {
        dim3 grid(QKVCOLS / 128, MROWS / 128);
        gemm_tf32_bias<<<grid, 256>>>(x, w_qkv, b_qkv, qkv,
                                      MROWS, QKVCOLS, DMODEL);
    }

    // 2) causal flash attention (tf32 tensor cores)
    {
        const int smem = (QT * QPAD + 2 * KT * QPAD + QT * QPAD) * 4; // 104448 B
        static int attr_set = 0;
        cudaFuncSetAttribute(attn_tf32,
                             cudaFuncAttributeMaxDynamicSharedMemorySize, smem);
        (void)attr_set;
        dim3 grid(BB * NH, NTOK / QT);    // (64, 16)
        attn_tf32<<<grid, 256, smem>>>(qkv, att);
    }

    // 3) output projection (tf32 tensor cores)
    {
        dim3 grid(DMODEL / 128, MROWS / 128);
        gemm_tf32_bias<<<grid, 256>>>(att, w_out, b_out, out,
                                      MROWS, DMODEL, DMODEL);
    }
}